// round 2
// baseline (speedup 1.0000x reference)
#include <cuda_runtime.h>
#include <math.h>

// ---------------------------------------------------------------------------
// FeedForwardQuantum fused kernel (fp32 baseline, round 1)
//   q[m,i]  = cos(x[m,i]) * cos(theta[i])            i < 8
//   h[m,f]  = relu( sum_i q[m,i]*W1[f,i] + b1[f] )   (recomputed per tile)
//   out[m,e]= sum_f h[m,f]*W2[e,f] + b2[e]
// GEMM2 is the dominant cost: M=32768, N=512, K=2048 (~69 GFLOP).
// ---------------------------------------------------------------------------

#define BM 128
#define BN 128
#define BK 16
#define NTHREADS 256   // 16x16 thread grid, 8x8 microtile each

#define E_DIM 512
#define F_DIM 2048
#define Q_DIM 8

// Scratch: W2 transposed to [F][E] so B-tile loads are coalesced.
// (device global array: allocation-free, per the harness rules)
__device__ float g_W2T[(size_t)F_DIM * E_DIM];

__global__ void transpose_W2_kernel(const float* __restrict__ W2) {
    __shared__ float t[32][33];
    const int e0 = blockIdx.x * 32;
    const int f0 = blockIdx.y * 32;
    const int tx = threadIdx.x;       // 0..31
    const int ty = threadIdx.y;       // 0..7
#pragma unroll
    for (int i = ty; i < 32; i += 8)
        t[i][tx] = W2[(size_t)(e0 + i) * F_DIM + f0 + tx];
    __syncthreads();
#pragma unroll
    for (int i = ty; i < 32; i += 8)
        g_W2T[(size_t)(f0 + i) * E_DIM + e0 + tx] = t[tx][i];
}

__global__ void __launch_bounds__(NTHREADS, 2)
ffq_fused_kernel(const float* __restrict__ x,
                 const float* __restrict__ theta,
                 const float* __restrict__ W1,
                 const float* __restrict__ b1,
                 const float* __restrict__ b2,
                 float* __restrict__ out) {
    __shared__ float sA[BK][BM];   // h chunk   [k][m]
    __shared__ float sB[BK][BN];   // W2T chunk [k][n]

    const int tid = threadIdx.x;
    const int m0  = blockIdx.y * BM;
    const int n0  = blockIdx.x * BN;

    // h-producer mapping: this thread owns token m, k-lanes {2j+khalf}
    const int m     = tid & 127;
    const int khalf = tid >> 7;       // 0 or 1

    // consumer mapping: 16x16 grid of 8x8 microtiles
    const int tx = tid & 15;          // col group  (n = tx*8 .. +7)
    const int ty = tid >> 4;          // row group  (m = ty*8 .. +7)

    // ---- per-thread q (token m), cached in registers for the whole kernel
    float rq[Q_DIM];
    {
        const float* xr = x + (size_t)(m0 + m) * E_DIM;
#pragma unroll
        for (int i = 0; i < Q_DIM; i++)
            rq[i] = cosf(xr[i]) * cosf(theta[i]);
    }

    float acc[8][8];
#pragma unroll
    for (int u = 0; u < 8; u++)
#pragma unroll
        for (int v = 0; v < 8; v++)
            acc[u][v] = 0.0f;

    const int n_chunks = F_DIM / BK;   // 128
    for (int kt = 0; kt < n_chunks; kt++) {
        const int f0 = kt * BK;

        // ---- produce h chunk: sA[k][m] = relu(q . W1[f0+k] + b1[f0+k])
        // All 32 lanes of a warp share (f0+k): W1/b1 loads are warp-uniform.
#pragma unroll
        for (int j = 0; j < 8; j++) {
            const int k = 2 * j + khalf;
            const float* w = W1 + (size_t)(f0 + k) * Q_DIM;
            float h = __ldg(&b1[f0 + k]);
#pragma unroll
            for (int i = 0; i < Q_DIM; i++)
                h = fmaf(rq[i], __ldg(&w[i]), h);
            sA[k][m] = fmaxf(h, 0.0f);
        }

        // ---- load W2T tile: sB[k][n] = W2T[f0+k][n0+n]   (coalesced float4)
#pragma unroll
        for (int j = 0; j < 2; j++) {
            const int v  = tid + NTHREADS * j;   // 0..511 float4 slots
            const int k  = v >> 5;               // /32 float4 per row
            const int n4 = (v & 31) << 2;
            *(float4*)&sB[k][n4] =
                *(const float4*)&g_W2T[(size_t)(f0 + k) * E_DIM + n0 + n4];
        }

        __syncthreads();

        // ---- 128x128x16 FMA block
#pragma unroll
        for (int kk = 0; kk < BK; kk++) {
            float a[8], b[8];
            *(float4*)&a[0] = *(const float4*)&sA[kk][ty * 8];
            *(float4*)&a[4] = *(const float4*)&sA[kk][ty * 8 + 4];
            *(float4*)&b[0] = *(const float4*)&sB[kk][tx * 8];
            *(float4*)&b[4] = *(const float4*)&sB[kk][tx * 8 + 4];
#pragma unroll
            for (int u = 0; u < 8; u++)
#pragma unroll
                for (int v = 0; v < 8; v++)
                    acc[u][v] = fmaf(a[u], b[v], acc[u][v]);
        }

        __syncthreads();
    }

    // ---- epilogue: add b2, write out
#pragma unroll
    for (int u = 0; u < 8; u++) {
        float* orow = out + (size_t)(m0 + ty * 8 + u) * E_DIM + n0 + tx * 8;
        float4 r0, r1;
        r0.x = acc[u][0] + b2[n0 + tx * 8 + 0];
        r0.y = acc[u][1] + b2[n0 + tx * 8 + 1];
        r0.z = acc[u][2] + b2[n0 + tx * 8 + 2];
        r0.w = acc[u][3] + b2[n0 + tx * 8 + 3];
        r1.x = acc[u][4] + b2[n0 + tx * 8 + 4];
        r1.y = acc[u][5] + b2[n0 + tx * 8 + 5];
        r1.z = acc[u][6] + b2[n0 + tx * 8 + 6];
        r1.w = acc[u][7] + b2[n0 + tx * 8 + 7];
        *(float4*)&orow[0] = r0;
        *(float4*)&orow[4] = r1;
    }
}

extern "C" void kernel_launch(void* const* d_in, const int* in_sizes, int n_in,
                              void* d_out, int out_size) {
    const float* x     = (const float*)d_in[0];
    const float* theta = (const float*)d_in[1];
    const float* W1    = (const float*)d_in[2];
    const float* b1    = (const float*)d_in[3];
    const float* W2    = (const float*)d_in[4];
    const float* b2    = (const float*)d_in[5];
    float* out = (float*)d_out;

    const int M = in_sizes[0] / E_DIM;   // B*S = 32768

    // 1) transpose W2 -> g_W2T   (graph-captured every replay; ~8 MB traffic)
    transpose_W2_kernel<<<dim3(E_DIM / 32, F_DIM / 32), dim3(32, 8)>>>(W2);

    // 2) fused quantum-layer + MLP
    dim3 grid(E_DIM / BN, M / BM);
    ffq_fused_kernel<<<grid, NTHREADS>>>(x, theta, W1, b1, b2, out);
}

// round 4
// speedup vs baseline: 2.8618x; 2.8618x over previous
#include <cuda_runtime.h>
#include <math.h>
#include <stdint.h>

// ---------------------------------------------------------------------------
// FeedForwardQuantum, round 3: fused mma.sync tf32 GEMM (sm_80+ ISA — the
// harness builds via compute_103, which rejects tcgen05; HMMA path instead).
//   q[m,i] = cos(x[m,i]) * cos(theta[i])    -> SMEM once   (fp32)
//   h[m,f] = relu(q . W1[f,:] + b1[f])      -> per k-tile, fp32, tf32-rounded
//   out    = h @ W2^T + b2                  -> mma.sync m16n8k8 tf32
// CTA: 128(M) x 256(N), BK=32, 512 threads, 4x4 warps of 32x64 tiles,
// double-buffered SMEM, grid (2, 256).
// ---------------------------------------------------------------------------

#define E_DIM 512
#define F_DIM 2048
#define BM    128
#define BN    256
#define BK    32
#define NT    512
#define NKT   (F_DIM / BK)   // 64
#define AS    36             // row stride (floats): BK + 4 pad, conflict-free frags

// SMEM float offsets
#define QS_OFF 0                    // q: 128 x 8          = 1024 floats
#define A_OFF  1024                 // sA: 2 x 128 x 36    = 9216 floats
#define B_OFF  (1024 + 9216)        // sB: 2 x 256 x 36    = 18432 floats
#define SMEM_FLOATS (1024 + 9216 + 18432)
#define SMEM_BYTES  (SMEM_FLOATS * 4)   // 114688 B

__device__ __forceinline__ float to_tf32(float v) {
    float r;
    asm("cvt.rna.tf32.f32 %0, %1;" : "=f"(r) : "f"(v));
    return r;
}

__device__ __forceinline__ void mma_tf32(float* d, const float* a, const float* b) {
    asm volatile(
        "mma.sync.aligned.m16n8k8.row.col.f32.tf32.tf32.f32 "
        "{%0,%1,%2,%3}, {%4,%5,%6,%7}, {%8,%9}, {%0,%1,%2,%3};\n"
        : "+f"(d[0]), "+f"(d[1]), "+f"(d[2]), "+f"(d[3])
        : "r"(__float_as_uint(a[0])), "r"(__float_as_uint(a[1])),
          "r"(__float_as_uint(a[2])), "r"(__float_as_uint(a[3])),
          "r"(__float_as_uint(b[0])), "r"(__float_as_uint(b[1])));
}

__global__ void __launch_bounds__(NT, 1)
ffq_mma_kernel(const float* __restrict__ x, const float* __restrict__ theta,
               const float* __restrict__ W1, const float* __restrict__ b1,
               const float* __restrict__ W2, const float* __restrict__ b2,
               float* __restrict__ out)
{
    extern __shared__ float sm[];
    float* qS = sm + QS_OFF;

    const int tid  = threadIdx.x;
    const int lane = tid & 31;
    const int wid  = tid >> 5;
    const int m0   = blockIdx.y * BM;
    const int n0   = blockIdx.x * BN;

    // warp tile origin within CTA tile
    const int mw = (wid & 3) * 32;
    const int nw = (wid >> 2) * 64;
    const int fr = lane >> 2;    // fragment row group 0..7
    const int fc = lane & 3;     // fragment col group 0..3

    // ---- prologue: q[m][0:8] = cos(x)*cos(theta) into SMEM ----
    if (tid < BM) {
        const float4* xr = (const float4*)(x + (size_t)(m0 + tid) * E_DIM);
        float4 x0 = __ldg(xr), x1 = __ldg(xr + 1);
        float4 t0 = __ldg((const float4*)theta);
        float4 t1 = __ldg((const float4*)theta + 1);
        float4 q0, q1;
        q0.x = cosf(x0.x) * cosf(t0.x);
        q0.y = cosf(x0.y) * cosf(t0.y);
        q0.z = cosf(x0.z) * cosf(t0.z);
        q0.w = cosf(x0.w) * cosf(t0.w);
        q1.x = cosf(x1.x) * cosf(t1.x);
        q1.y = cosf(x1.y) * cosf(t1.y);
        q1.z = cosf(x1.z) * cosf(t1.z);
        q1.w = cosf(x1.w) * cosf(t1.w);
        ((float4*)(qS + tid * 8))[0] = q0;
        ((float4*)(qS + tid * 8))[1] = q1;
    }
    __syncthreads();

    // h-producer mapping: f-lane = tid&31, tokens hg*8..hg*8+7 (hg = warp id)
    const int hf = tid & 31;
    const int hg = tid >> 5;

    float4 bv[4];   // W2 prefetch regs
    float  hv[8];   // h prefetch regs

    // ---- prefetch k-tile 0 ----
    {
        const int f0 = 0;
#pragma unroll
        for (int j = 0; j < 4; j++) {
            int v = tid + NT * j;          // 0..2047
            int row = v >> 3, c4 = v & 7;
            bv[j] = __ldcs((const float4*)(W2 + (size_t)(n0 + row) * F_DIM + f0 + c4 * 4));
        }
        const int f = f0 + hf;
        float4 wa = __ldg((const float4*)(W1 + (size_t)f * 8));
        float4 wb = __ldg((const float4*)(W1 + (size_t)f * 8) + 1);
        float  bb = __ldg(b1 + f);
#pragma unroll
        for (int j = 0; j < 8; j++) {
            const float4* qp = (const float4*)(qS + (hg * 8 + j) * 8);
            float4 qa = qp[0], qb = qp[1];   // warp-broadcast LDS
            float h = bb;
            h = fmaf(qa.x, wa.x, h); h = fmaf(qa.y, wa.y, h);
            h = fmaf(qa.z, wa.z, h); h = fmaf(qa.w, wa.w, h);
            h = fmaf(qb.x, wb.x, h); h = fmaf(qb.y, wb.y, h);
            h = fmaf(qb.z, wb.z, h); h = fmaf(qb.w, wb.w, h);
            hv[j] = fmaxf(h, 0.0f);
        }
    }
    // ---- store k-tile 0 into buffer 0 ----
    {
        float* A = sm + A_OFF;
        float* B = sm + B_OFF;
#pragma unroll
        for (int j = 0; j < 8; j++)
            A[(hg * 8 + j) * AS + hf] = to_tf32(hv[j]);
#pragma unroll
        for (int j = 0; j < 4; j++) {
            int v = tid + NT * j;
            int row = v >> 3, c4 = v & 7;
            float4 t = bv[j];
            t.x = to_tf32(t.x); t.y = to_tf32(t.y);
            t.z = to_tf32(t.z); t.w = to_tf32(t.w);
            *(float4*)(B + row * AS + c4 * 4) = t;
        }
    }
    __syncthreads();

    float d[2][8][4];
#pragma unroll
    for (int mf = 0; mf < 2; mf++)
#pragma unroll
        for (int nf = 0; nf < 8; nf++)
#pragma unroll
            for (int i = 0; i < 4; i++)
                d[mf][nf][i] = 0.0f;

    // ---- mainloop ----
    for (int kt = 0; kt < NKT; kt++) {
        const int p = kt & 1;

        // prefetch next k-tile into registers (overlaps with MMA below)
        if (kt + 1 < NKT) {
            const int f0 = (kt + 1) * BK;
#pragma unroll
            for (int j = 0; j < 4; j++) {
                int v = tid + NT * j;
                int row = v >> 3, c4 = v & 7;
                bv[j] = __ldcs((const float4*)(W2 + (size_t)(n0 + row) * F_DIM + f0 + c4 * 4));
            }
            const int f = f0 + hf;
            float4 wa = __ldg((const float4*)(W1 + (size_t)f * 8));
            float4 wb = __ldg((const float4*)(W1 + (size_t)f * 8) + 1);
            float  bb = __ldg(b1 + f);
#pragma unroll
            for (int j = 0; j < 8; j++) {
                const float4* qp = (const float4*)(qS + (hg * 8 + j) * 8);
                float4 qa = qp[0], qb = qp[1];
                float h = bb;
                h = fmaf(qa.x, wa.x, h); h = fmaf(qa.y, wa.y, h);
                h = fmaf(qa.z, wa.z, h); h = fmaf(qa.w, wa.w, h);
                h = fmaf(qb.x, wb.x, h); h = fmaf(qb.y, wb.y, h);
                h = fmaf(qb.z, wb.z, h); h = fmaf(qb.w, wb.w, h);
                hv[j] = fmaxf(h, 0.0f);
            }
        }

        // MMA over buffer p
        {
            const float* A = sm + A_OFF + p * (BM * AS);
            const float* B = sm + B_OFF + p * (BN * AS);
#pragma unroll
            for (int ks = 0; ks < 4; ks++) {
                const int k0 = ks * 8;
                float a[2][4], b[8][2];
#pragma unroll
                for (int mf = 0; mf < 2; mf++) {
                    const int mb = mw + mf * 16;
                    a[mf][0] = A[(mb + fr) * AS + k0 + fc];
                    a[mf][1] = A[(mb + fr + 8) * AS + k0 + fc];
                    a[mf][2] = A[(mb + fr) * AS + k0 + fc + 4];
                    a[mf][3] = A[(mb + fr + 8) * AS + k0 + fc + 4];
                }
#pragma unroll
                for (int nf = 0; nf < 8; nf++) {
                    const int nb = nw + nf * 8 + fr;
                    b[nf][0] = B[nb * AS + k0 + fc];
                    b[nf][1] = B[nb * AS + k0 + fc + 4];
                }
#pragma unroll
                for (int mf = 0; mf < 2; mf++)
#pragma unroll
                    for (int nf = 0; nf < 8; nf++)
                        mma_tf32(d[mf][nf], a[mf], b[nf]);
            }
        }

        // store next k-tile into the other buffer
        if (kt + 1 < NKT) {
            float* A = sm + A_OFF + (1 - p) * (BM * AS);
            float* B = sm + B_OFF + (1 - p) * (BN * AS);
#pragma unroll
            for (int j = 0; j < 8; j++)
                A[(hg * 8 + j) * AS + hf] = to_tf32(hv[j]);
#pragma unroll
            for (int j = 0; j < 4; j++) {
                int v = tid + NT * j;
                int row = v >> 3, c4 = v & 7;
                float4 t = bv[j];
                t.x = to_tf32(t.x); t.y = to_tf32(t.y);
                t.z = to_tf32(t.z); t.w = to_tf32(t.w);
                *(float4*)(B + row * AS + c4 * 4) = t;
            }
        }
        __syncthreads();
    }

    // ---- epilogue: out = d + b2 (STG.64, full 32B sectors) ----
    float b2v[8][2];
#pragma unroll
    for (int nf = 0; nf < 8; nf++) {
        b2v[nf][0] = __ldg(b2 + n0 + nw + nf * 8 + fc * 2);
        b2v[nf][1] = __ldg(b2 + n0 + nw + nf * 8 + fc * 2 + 1);
    }
#pragma unroll
    for (int mf = 0; mf < 2; mf++) {
#pragma unroll
        for (int i2 = 0; i2 < 2; i2++) {
            const int row = m0 + mw + mf * 16 + fr + i2 * 8;
            float* orow = out + (size_t)row * E_DIM + n0 + nw + fc * 2;
#pragma unroll
            for (int nf = 0; nf < 8; nf++) {
                float2 v;
                v.x = d[mf][nf][i2 * 2 + 0] + b2v[nf][0];
                v.y = d[mf][nf][i2 * 2 + 1] + b2v[nf][1];
                *(float2*)(orow + nf * 8) = v;
            }
        }
    }
}

extern "C" void kernel_launch(void* const* d_in, const int* in_sizes, int n_in,
                              void* d_out, int out_size) {
    const float* x     = (const float*)d_in[0];
    const float* theta = (const float*)d_in[1];
    const float* W1    = (const float*)d_in[2];
    const float* b1    = (const float*)d_in[3];
    const float* W2    = (const float*)d_in[4];
    const float* b2    = (const float*)d_in[5];
    float* out = (float*)d_out;

    const int M = in_sizes[0] / E_DIM;   // 32768

    cudaFuncSetAttribute(ffq_mma_kernel,
                         cudaFuncAttributeMaxDynamicSharedMemorySize, SMEM_BYTES);
    dim3 grid(E_DIM / BN, M / BM);
    ffq_mma_kernel<<<grid, NT, SMEM_BYTES>>>(x, theta, W1, b1, W2, b2, out);
}

// round 7
// speedup vs baseline: 2.9449x; 1.0290x over previous
#include <cuda_runtime.h>
#include <math.h>
#include <stdint.h>

// ---------------------------------------------------------------------------
// FeedForwardQuantum, round 4: fused mma.sync tf32, stall-oriented redesign.
//  - CTA 128(M) x 128(N), 256 threads (8 warps, warp tile 32x64), 2 CTAs/SM
//  - W2 pre-rounded to tf32 AND stored in k-permuted + bank-swizzled layout
//    (prep kernel) so B tiles stream via cp.async.cg with zero reg staging
//  - fragment loads are LDS.128 (k-pair permute), conflict-free
//  - h = relu(q.W1+b1) recomputed per k-tile (K=8, cheap), STS direct
// ---------------------------------------------------------------------------

#define E_DIM 512
#define F_DIM 2048
#define BM    128
#define BN    128
#define BK    32
#define NT    256
#define NKT   (F_DIM / BK)       // 64

// dynamic SMEM float offsets
#define QS_OFF 0                 // q: 128 x 8                = 1024
#define A_OFF  1024              // A: 2 x 128 x 32           = 8192
#define B_OFF  (1024 + 8192)     // B: 2 x 128 x 32           = 8192
#define SMEM_BYTES ((1024 + 8192 + 8192) * 4)   // 69632 B

// W2 pre-rounded + permuted scratch
__device__ float g_W2r[(size_t)E_DIM * F_DIM];

__device__ __forceinline__ float to_tf32(float v) {
    float r;
    asm("cvt.rna.tf32.f32 %0, %1;" : "=f"(r) : "f"(v));
    return r;
}

__device__ __forceinline__ void mma_tf32(float* d, float a0, float a1, float a2, float a3,
                                         float b0, float b1) {
    asm volatile(
        "mma.sync.aligned.m16n8k8.row.col.f32.tf32.tf32.f32 "
        "{%0,%1,%2,%3}, {%4,%5,%6,%7}, {%8,%9}, {%0,%1,%2,%3};\n"
        : "+f"(d[0]), "+f"(d[1]), "+f"(d[2]), "+f"(d[3])
        : "r"(__float_as_uint(a0)), "r"(__float_as_uint(a1)),
          "r"(__float_as_uint(a2)), "r"(__float_as_uint(a3)),
          "r"(__float_as_uint(b0)), "r"(__float_as_uint(b1)));
}

__device__ __forceinline__ void cp16(uint32_t dst, const void* src) {
    asm volatile("cp.async.cg.shared.global [%0], [%1], 16;" :: "r"(dst), "l"(src) : "memory");
}

// ---------------------------------------------------------------------------
// prep: g_W2r[n][t*32+q] = tf32( W2[n][t*32 + k(q,n)] )
//   q = slot_sw*4+g;  slot = slot_sw ^ ((n&1)<<2);  kg=slot>>2; fc=slot&3;
//   k  = kg*16 + fc + 4*g
// ---------------------------------------------------------------------------
__global__ void prep_W2_kernel(const float* __restrict__ W2) {
    int idx = blockIdx.x * 256 + threadIdx.x;       // 0 .. 512*2048-1
    int n = idx >> 11;
    int c = idx & 2047;
    int t = c >> 5, q = c & 31;
    int slot = (q >> 2) ^ ((n & 1) << 2);
    int g = q & 3;
    int k = ((slot >> 2) << 4) + (slot & 3) + (g << 2);
    g_W2r[idx] = to_tf32(W2[(size_t)n * F_DIM + t * 32 + k]);
}

__global__ void __launch_bounds__(NT, 2)
ffq_mma_kernel(const float* __restrict__ x, const float* __restrict__ theta,
               const float* __restrict__ W1, const float* __restrict__ b1,
               const float* __restrict__ b2, float* __restrict__ out)
{
    extern __shared__ float sm[];
    float* qS = sm + QS_OFF;
    const uint32_t smB_u32 = (uint32_t)__cvta_generic_to_shared(sm + B_OFF);

    const int tid  = threadIdx.x;
    const int lane = tid & 31;
    const int wid  = tid >> 5;
    const int m0   = blockIdx.y * BM;
    const int n0   = blockIdx.x * BN;

    // warp tile: 4 (m) x 2 (n) grid of 32x64 tiles
    const int mw = (wid & 3) * 32;
    const int nw = (wid >> 2) * 64;
    const int fr = lane >> 2;
    const int fc = lane & 3;
    const int sw = (fr & 1) << 2;          // frag-load row-parity swizzle

    // h-producer: f-lane hf = tid&31, tokens tg*16..+15
    const int hf = tid & 31;
    const int tg = tid >> 5;
    const int h_kg = hf >> 4;
    const int h_lo = hf & 15;
    const int h_fc = h_lo & 3;
    const int h_g  = h_lo >> 2;
    const int h_slot = (h_kg << 2) | h_fc;
    const int q_even = (h_slot << 2) + h_g;               // m even
    const int q_odd  = (((h_slot ^ 4)) << 2) + h_g;       // m odd

    // ---- cp.async B(0) -> buf0 (issued first to hide latency) ----
    {
        const float* src0 = g_W2r + (size_t)n0 * F_DIM;   // kt = 0
#pragma unroll
        for (int j = 0; j < 4; j++) {
            int c = tid + NT * j;                 // 0..1023
            int row = c >> 3, slot = c & 7;
            cp16(smB_u32 + (uint32_t)(row * 32 + slot * 4) * 4,
                 src0 + (size_t)row * F_DIM + slot * 4);
        }
        asm volatile("cp.async.commit_group;" ::: "memory");
    }

    // ---- q[m][0:8] = cos(x)*cos(theta) ----
    if (tid < BM) {
        const float4* xr = (const float4*)(x + (size_t)(m0 + tid) * E_DIM);
        float4 x0 = __ldg(xr), x1 = __ldg(xr + 1);
        float4 t0 = __ldg((const float4*)theta);
        float4 t1 = __ldg((const float4*)theta + 1);
        float4 q0, q1;
        q0.x = cosf(x0.x) * cosf(t0.x);
        q0.y = cosf(x0.y) * cosf(t0.y);
        q0.z = cosf(x0.z) * cosf(t0.z);
        q0.w = cosf(x0.w) * cosf(t0.w);
        q1.x = cosf(x1.x) * cosf(t1.x);
        q1.y = cosf(x1.y) * cosf(t1.y);
        q1.z = cosf(x1.z) * cosf(t1.z);
        q1.w = cosf(x1.w) * cosf(t1.w);
        ((float4*)(qS + tid * 8))[0] = q0;
        ((float4*)(qS + tid * 8))[1] = q1;
    }
    __syncthreads();

    // ---- h(0) -> A buf0 ----
    {
        float* A = sm + A_OFF;
        const int f = hf;                 // kt = 0
        float4 wa = __ldg((const float4*)(W1 + (size_t)f * 8));
        float4 wb = __ldg((const float4*)(W1 + (size_t)f * 8) + 1);
        float  bb = __ldg(b1 + f);
#pragma unroll
        for (int j = 0; j < 16; j++) {
            const int m = tg * 16 + j;
            const float4* qp = (const float4*)(qS + m * 8);
            float4 qa = qp[0], qb = qp[1];
            float h = bb;
            h = fmaf(qa.x, wa.x, h); h = fmaf(qa.y, wa.y, h);
            h = fmaf(qa.z, wa.z, h); h = fmaf(qa.w, wa.w, h);
            h = fmaf(qb.x, wb.x, h); h = fmaf(qb.y, wb.y, h);
            h = fmaf(qb.z, wb.z, h); h = fmaf(qb.w, wb.w, h);
            A[m * 32 + ((m & 1) ? q_odd : q_even)] = to_tf32(fmaxf(h, 0.0f));
        }
    }

    float d[2][8][4];
#pragma unroll
    for (int mf = 0; mf < 2; mf++)
#pragma unroll
        for (int nf = 0; nf < 8; nf++)
#pragma unroll
            for (int i = 0; i < 4; i++)
                d[mf][nf][i] = 0.0f;

    // ---- mainloop ----
    for (int kt = 0; kt < NKT; kt++) {
        const int p = kt & 1;

        asm volatile("cp.async.wait_group 0;" ::: "memory");
        __syncthreads();   // A(p), B(p) ready; all prior-tile reads complete

        // issue cp.async B(kt+1) -> buf(1-p)   (safe: after barrier)
        if (kt + 1 < NKT) {
            const float* srcN = g_W2r + (size_t)n0 * F_DIM + (kt + 1) * BK;
            const uint32_t dstB = smB_u32 + (uint32_t)((1 - p) * 4096) * 4;
#pragma unroll
            for (int j = 0; j < 4; j++) {
                int c = tid + NT * j;
                int row = c >> 3, slot = c & 7;
                cp16(dstB + (uint32_t)(row * 32 + slot * 4) * 4,
                     srcN + (size_t)row * F_DIM + slot * 4);
            }
            asm volatile("cp.async.commit_group;" ::: "memory");

            // h(kt+1) -> A(1-p)
            float* A = sm + A_OFF + (1 - p) * 4096;
            const int f = (kt + 1) * BK + hf;
            float4 wa = __ldg((const float4*)(W1 + (size_t)f * 8));
            float4 wb = __ldg((const float4*)(W1 + (size_t)f * 8) + 1);
            float  bb = __ldg(b1 + f);
#pragma unroll
            for (int j = 0; j < 16; j++) {
                const int m = tg * 16 + j;
                const float4* qp = (const float4*)(qS + m * 8);
                float4 qa = qp[0], qb = qp[1];
                float h = bb;
                h = fmaf(qa.x, wa.x, h); h = fmaf(qa.y, wa.y, h);
                h = fmaf(qa.z, wa.z, h); h = fmaf(qa.w, wa.w, h);
                h = fmaf(qb.x, wb.x, h); h = fmaf(qb.y, wb.y, h);
                h = fmaf(qb.z, wb.z, h); h = fmaf(qb.w, wb.w, h);
                A[m * 32 + ((m & 1) ? q_odd : q_even)] = to_tf32(fmaxf(h, 0.0f));
            }
        }

        // ---- MMA over buffers p ----
        {
            const float* A = sm + A_OFF + p * 4096;
            const float* B = sm + B_OFF + p * 4096;
#pragma unroll
            for (int kg = 0; kg < 2; kg++) {
                const int slotA = (((kg << 2) | fc) ^ sw) << 2;
                float4 va[2][2];
#pragma unroll
                for (int mf = 0; mf < 2; mf++) {
                    const int r = mw + mf * 16 + fr;
                    va[mf][0] = *(const float4*)(A + r * 32 + slotA);
                    va[mf][1] = *(const float4*)(A + (r + 8) * 32 + slotA);
                }
#pragma unroll
                for (int nf = 0; nf < 8; nf++) {
                    const int nb = nw + nf * 8 + fr;
                    float4 vb = *(const float4*)(B + nb * 32 + slotA);
#pragma unroll
                    for (int mf = 0; mf < 2; mf++) {
                        mma_tf32(d[mf][nf],
                                 va[mf][0].x, va[mf][1].x, va[mf][0].y, va[mf][1].y,
                                 vb.x, vb.y);
                        mma_tf32(d[mf][nf],
                                 va[mf][0].z, va[mf][1].z, va[mf][0].w, va[mf][1].w,
                                 vb.z, vb.w);
                    }
                }
            }
        }
    }

    // ---- epilogue: out = d + b2 ----
    float b2v[8][2];
#pragma unroll
    for (int nf = 0; nf < 8; nf++) {
        b2v[nf][0] = __ldg(b2 + n0 + nw + nf * 8 + fc * 2);
        b2v[nf][1] = __ldg(b2 + n0 + nw + nf * 8 + fc * 2 + 1);
    }
#pragma unroll
    for (int mf = 0; mf < 2; mf++) {
#pragma unroll
        for (int i2 = 0; i2 < 2; i2++) {
            const int row = m0 + mw + mf * 16 + fr + i2 * 8;
            float* orow = out + (size_t)row * E_DIM + n0 + nw + fc * 2;
#pragma unroll
            for (int nf = 0; nf < 8; nf++) {
                float2 v;
                v.x = d[mf][nf][i2 * 2 + 0] + b2v[nf][0];
                v.y = d[mf][nf][i2 * 2 + 1] + b2v[nf][1];
                *(float2*)(orow + nf * 8) = v;
            }
        }
    }
}

extern "C" void kernel_launch(void* const* d_in, const int* in_sizes, int n_in,
                              void* d_out, int out_size) {
    const float* x     = (const float*)d_in[0];
    const float* theta = (const float*)d_in[1];
    const float* W1    = (const float*)d_in[2];
    const float* b1    = (const float*)d_in[3];
    const float* W2    = (const float*)d_in[4];
    const float* b2    = (const float*)d_in[5];
    float* out = (float*)d_out;

    const int M = in_sizes[0] / E_DIM;   // 32768

    prep_W2_kernel<<<(E_DIM * F_DIM) / 256, 256>>>(W2);

    cudaFuncSetAttribute(ffq_mma_kernel,
                         cudaFuncAttributeMaxDynamicSharedMemorySize, SMEM_BYTES);
    dim3 grid(E_DIM / BN, M / BM);
    ffq_mma_kernel<<<grid, NT, SMEM_BYTES>>>(x, theta, W1, b1, b2, out);
}

// round 8
// speedup vs baseline: 3.4797x; 1.1816x over previous
#include <cuda_runtime.h>
#include <math.h>
#include <stdint.h>

// ---------------------------------------------------------------------------
// FeedForwardQuantum, round 7: BOTH GEMMs on tensor pipe.
//   GEMM1 (h = relu(q @ W1^T + b1), K=8) via mma.sync m16n8k8: q held in the
//   A-fragment registers forever; B-rows permuted so the accumulator packs
//   into STS.128 writes in the k-permuted A-tile layout (consumer unchanged).
//   GEMM2 (out = h @ W2^T + b2) identical to R4 (validated): cp.async B tiles
//   from pre-rounded/permuted g_W2r, LDS.128 fragments, m16n8k8 tf32.
// CTA 128x128, 256 thr, 8 warps (warp tile 32x64), double buffer, 2 CTAs/SM.
// ---------------------------------------------------------------------------

#define E_DIM 512
#define F_DIM 2048
#define BM    128
#define BN    128
#define BK    32
#define NT    256
#define NKT   (F_DIM / BK)       // 64

#define A_OFF 0                  // A: 2 x 128 x 32 floats = 8192
#define B_OFF 8192               // B: 2 x 128 x 32 floats = 8192
#define SMEM_BYTES (16384 * 4)   // 65536 B

__device__ float g_W2r[(size_t)E_DIM * F_DIM];
__device__ float g_W1r[(size_t)F_DIM * 8];

__device__ __forceinline__ float to_tf32(float v) {
    float r;
    asm("cvt.rna.tf32.f32 %0, %1;" : "=f"(r) : "f"(v));
    return r;
}

__device__ __forceinline__ void mma_tf32(float* d, float a0, float a1, float a2, float a3,
                                         float b0, float b1) {
    asm volatile(
        "mma.sync.aligned.m16n8k8.row.col.f32.tf32.tf32.f32 "
        "{%0,%1,%2,%3}, {%4,%5,%6,%7}, {%8,%9}, {%0,%1,%2,%3};\n"
        : "+f"(d[0]), "+f"(d[1]), "+f"(d[2]), "+f"(d[3])
        : "r"(__float_as_uint(a0)), "r"(__float_as_uint(a1)),
          "r"(__float_as_uint(a2)), "r"(__float_as_uint(a3)),
          "r"(__float_as_uint(b0)), "r"(__float_as_uint(b1)));
}

__device__ __forceinline__ void cp16(uint32_t dst, const void* src) {
    asm volatile("cp.async.cg.shared.global [%0], [%1], 16;" :: "r"(dst), "l"(src) : "memory");
}

// prep W2: tf32-round + k-permute + row-parity swizzle (identical to R4)
__global__ void prep_W2_kernel(const float* __restrict__ W2) {
    int idx = blockIdx.x * 256 + threadIdx.x;
    int n = idx >> 11;
    int c = idx & 2047;
    int t = c >> 5, q = c & 31;
    int slot = (q >> 2) ^ ((n & 1) << 2);
    int g = q & 3;
    int k = ((slot >> 2) << 4) + (slot & 3) + (g << 2);
    g_W2r[idx] = to_tf32(W2[(size_t)n * F_DIM + t * 32 + k]);
}

// prep W1: plain tf32 rounding
__global__ void prep_W1_kernel(const float* __restrict__ W1) {
    int i = blockIdx.x * 256 + threadIdx.x;   // 16384 total
    g_W1r[i] = to_tf32(W1[i]);
}

__global__ void __launch_bounds__(NT, 2)
ffq_mma_kernel(const float* __restrict__ x, const float* __restrict__ theta,
               const float* __restrict__ b1, const float* __restrict__ b2,
               float* __restrict__ out)
{
    extern __shared__ float sm[];
    const uint32_t smB_u32 = (uint32_t)__cvta_generic_to_shared(sm + B_OFF);

    const int tid  = threadIdx.x;
    const int lane = tid & 31;
    const int wid  = tid >> 5;
    const int m0   = blockIdx.y * BM;
    const int n0   = blockIdx.x * BN;

    // GEMM2 warp tile: 4(m) x 2(n) of 32x64
    const int mw = (wid & 3) * 32;
    const int nw = (wid >> 2) * 64;
    const int fr = lane >> 2;
    const int fc = lane & 3;
    const int sw = (fr & 1) << 2;

    // GEMM1 mapping: warp wid handles tokens wid*16..+15
    const int mA_t = wid * 16 + fr;       // tile-local token rows
    const int mB_t = mA_t + 8;
    const int permfr = (fr >> 1) | ((fr & 1) << 2);

    // ---- q A-fragment (registers, whole kernel) ----
    float a0, a1, a2, a3;
    {
        const float* xA = x + (size_t)(m0 + mA_t) * E_DIM;
        const float* xB = x + (size_t)(m0 + mB_t) * E_DIM;
        float t0 = cosf(__ldg(theta + fc));
        float t1 = cosf(__ldg(theta + fc + 4));
        a0 = to_tf32(cosf(__ldg(xA + fc))     * t0);
        a1 = to_tf32(cosf(__ldg(xB + fc))     * t0);
        a2 = to_tf32(cosf(__ldg(xA + fc + 4)) * t1);
        a3 = to_tf32(cosf(__ldg(xB + fc + 4)) * t1);
    }

    // ---- cp.async source/dst precompute ----
    const float* w2src[4];
    uint32_t     w2dst[4];
#pragma unroll
    for (int j = 0; j < 4; j++) {
        int c = tid + NT * j;
        int row = c >> 3, slot = c & 7;
        w2src[j] = g_W2r + (size_t)(n0 + row) * F_DIM + slot * 4;
        w2dst[j] = smB_u32 + (uint32_t)(row * 32 + slot * 4) * 4;
    }

    // GEMM1 pointers (tile f0=0 first)
    const float* w1p = g_W1r + (size_t)permfr * 8 + fc;
    const float* b1p = b1 + fc;
    float* Arow0 = sm + A_OFF + mA_t * 32;
    float* Arow1 = sm + A_OFF + mB_t * 32;

    // ---- h producer: GEMM1 via mma, packs STS.128 into permuted layout ----
    auto produce_h = [&](float* A0, float* A1) {
#pragma unroll
        for (int kg = 0; kg < 2; kg++) {
            float bw0  = __ldg(w1p + kg * 128);
            float bw1  = __ldg(w1p + kg * 128 + 4);
            float bw2  = __ldg(w1p + kg * 128 + 64);
            float bw3  = __ldg(w1p + kg * 128 + 68);
            float bi0  = __ldg(b1p + kg * 16);
            float bi1  = __ldg(b1p + kg * 16 + 4);
            float bi2  = __ldg(b1p + kg * 16 + 8);
            float bi3  = __ldg(b1p + kg * 16 + 12);
            float dh0[4] = {0.f, 0.f, 0.f, 0.f};
            float dh1[4] = {0.f, 0.f, 0.f, 0.f};
            mma_tf32(dh0, a0, a1, a2, a3, bw0, bw1);   // ng = 2kg
            mma_tf32(dh1, a0, a1, a2, a3, bw2, bw3);   // ng = 2kg+1
            float4 vA, vB;
            vA.x = to_tf32(fmaxf(dh0[0] + bi0, 0.f));
            vA.y = to_tf32(fmaxf(dh0[1] + bi1, 0.f));
            vA.z = to_tf32(fmaxf(dh1[0] + bi2, 0.f));
            vA.w = to_tf32(fmaxf(dh1[1] + bi3, 0.f));
            vB.x = to_tf32(fmaxf(dh0[2] + bi0, 0.f));
            vB.y = to_tf32(fmaxf(dh0[3] + bi1, 0.f));
            vB.z = to_tf32(fmaxf(dh1[2] + bi2, 0.f));
            vB.w = to_tf32(fmaxf(dh1[3] + bi3, 0.f));
            const int slotcol = (((kg << 2) | fc) ^ sw) << 2;
            *(float4*)(A0 + slotcol) = vA;
            *(float4*)(A1 + slotcol) = vB;
        }
        w1p += 256;   // next 32-f slice
        b1p += 32;
    };

    // ---- prologue: B(0) cp.async + h(0) ----
#pragma unroll
    for (int j = 0; j < 4; j++) { cp16(w2dst[j], w2src[j]); w2src[j] += 32; }
    asm volatile("cp.async.commit_group;" ::: "memory");
    produce_h(Arow0, Arow1);

    float d[2][8][4];
#pragma unroll
    for (int mf = 0; mf < 2; mf++)
#pragma unroll
        for (int nf = 0; nf < 8; nf++)
#pragma unroll
            for (int i = 0; i < 4; i++)
                d[mf][nf][i] = 0.0f;

    // ---- mainloop ----
    for (int kt = 0; kt < NKT; kt++) {
        const int p = kt & 1;

        asm volatile("cp.async.wait_group 0;" ::: "memory");
        __syncthreads();

        if (kt + 1 < NKT) {
            const uint32_t dofs = (uint32_t)((1 - p) * 16384);
#pragma unroll
            for (int j = 0; j < 4; j++) { cp16(w2dst[j] + dofs, w2src[j]); w2src[j] += 32; }
            asm volatile("cp.async.commit_group;" ::: "memory");
        }

        // GEMM2 MMA over buffer p
        {
            const float* A = sm + A_OFF + p * 4096;
            const float* B = sm + B_OFF + p * 4096;
#pragma unroll
            for (int kg = 0; kg < 2; kg++) {
                const int slotA = (((kg << 2) | fc) ^ sw) << 2;
                float4 va[2][2];
#pragma unroll
                for (int mf = 0; mf < 2; mf++) {
                    const int r = mw + mf * 16 + fr;
                    va[mf][0] = *(const float4*)(A + r * 32 + slotA);
                    va[mf][1] = *(const float4*)(A + (r + 8) * 32 + slotA);
                }
#pragma unroll
                for (int nf = 0; nf < 8; nf++) {
                    const int nb = nw + nf * 8 + fr;
                    float4 vb = *(const float4*)(B + nb * 32 + slotA);
#pragma unroll
                    for (int mf = 0; mf < 2; mf++) {
                        mma_tf32(d[mf][nf],
                                 va[mf][0].x, va[mf][1].x, va[mf][0].y, va[mf][1].y,
                                 vb.x, vb.y);
                        mma_tf32(d[mf][nf],
                                 va[mf][0].z, va[mf][1].z, va[mf][0].w, va[mf][1].w,
                                 vb.z, vb.w);
                    }
                }
            }
        }

        // GEMM1: produce h(kt+1) into A(1-p)
        if (kt + 1 < NKT) {
            float* A0 = Arow0 + (1 - p) * 4096;
            float* A1 = Arow1 + (1 - p) * 4096;
            produce_h(A0, A1);
        }
    }

    // ---- epilogue: out = d + b2 ----
    float b2v[8][2];
#pragma unroll
    for (int nf = 0; nf < 8; nf++) {
        b2v[nf][0] = __ldg(b2 + n0 + nw + nf * 8 + fc * 2);
        b2v[nf][1] = __ldg(b2 + n0 + nw + nf * 8 + fc * 2 + 1);
    }
#pragma unroll
    for (int mf = 0; mf < 2; mf++) {
#pragma unroll
        for (int i2 = 0; i2 < 2; i2++) {
            const int row = m0 + mw + mf * 16 + fr + i2 * 8;
            float* orow = out + (size_t)row * E_DIM + n0 + nw + fc * 2;
#pragma unroll
            for (int nf = 0; nf < 8; nf++) {
                float2 v;
                v.x = d[mf][nf][i2 * 2 + 0] + b2v[nf][0];
                v.y = d[mf][nf][i2 * 2 + 1] + b2v[nf][1];
                *(float2*)(orow + nf * 8) = v;
            }
        }
    }
}

extern "C" void kernel_launch(void* const* d_in, const int* in_sizes, int n_in,
                              void* d_out, int out_size) {
    const float* x     = (const float*)d_in[0];
    const float* theta = (const float*)d_in[1];
    const float* W1    = (const float*)d_in[2];
    const float* b1    = (const float*)d_in[3];
    const float* W2    = (const float*)d_in[4];
    const float* b2    = (const float*)d_in[5];
    float* out = (float*)d_out;

    const int M = in_sizes[0] / E_DIM;   // 32768

    prep_W1_kernel<<<(F_DIM * 8) / 256, 256>>>(W1);
    prep_W2_kernel<<<(E_DIM * F_DIM) / 256, 256>>>(W2);

    cudaFuncSetAttribute(ffq_mma_kernel,
                         cudaFuncAttributeMaxDynamicSharedMemorySize, SMEM_BYTES);
    dim3 grid(E_DIM / BN, M / BM);
    ffq_mma_kernel<<<grid, NT, SMEM_BYTES>>>(x, theta, b1, b2, out);
}

// round 11
// speedup vs baseline: 4.4807x; 1.2876x over previous
#include <cuda_runtime.h>
#include <math.h>
#include <stdint.h>

// ---------------------------------------------------------------------------
// FeedForwardQuantum, round 10: R8 design with the cp.async dst-stride fix
// (stage-internal row step is 32 rows = 4096 BYTES, not 16384).
//   - q lives in 8 regs/thread (A-frag of GEMM1) for the whole kernel
//   - GEMM1 (h) accumulator feeds GEMM2's A operand directly in registers
//     (B-row permute puts D cols on k = fc, fc+4); bias is accumulator init;
//     relu+cvt in regs. A never touches SMEM.
//   - B (W2 pre-rounded tf32, k-permuted, parity-swizzled) streams via a
//     3-stage cp.async pipeline; one syncthreads per k-tile guards reuse.
// CTA 128x128, 256 thr, 8 warps (warp tile 32x64), 2 CTAs/SM.
// ---------------------------------------------------------------------------

#define E_DIM 512
#define F_DIM 2048
#define BM    128
#define BN    128
#define BK    32
#define NT    256
#define NKT   (F_DIM / BK)        // 64
#define NSTG  3
#define BSTG_BYTES 16384          // 128 rows x 32 floats x 4 per stage
#define SMEM_BYTES (NSTG * BSTG_BYTES)   // 49152 B

__device__ float g_W2r[(size_t)E_DIM * F_DIM];
__device__ float g_W1r[(size_t)F_DIM * 8];

__device__ __forceinline__ float to_tf32(float v) {
    float r;
    asm("cvt.rna.tf32.f32 %0, %1;" : "=f"(r) : "f"(v));
    return r;
}

__device__ __forceinline__ void mma_tf32(float* d, float a0, float a1, float a2, float a3,
                                         float b0, float b1) {
    asm volatile(
        "mma.sync.aligned.m16n8k8.row.col.f32.tf32.tf32.f32 "
        "{%0,%1,%2,%3}, {%4,%5,%6,%7}, {%8,%9}, {%0,%1,%2,%3};\n"
        : "+f"(d[0]), "+f"(d[1]), "+f"(d[2]), "+f"(d[3])
        : "r"(__float_as_uint(a0)), "r"(__float_as_uint(a1)),
          "r"(__float_as_uint(a2)), "r"(__float_as_uint(a3)),
          "r"(__float_as_uint(b0)), "r"(__float_as_uint(b1)));
}

__device__ __forceinline__ void cp16(uint32_t dst, const void* src) {
    asm volatile("cp.async.cg.shared.global [%0], [%1], 16;" :: "r"(dst), "l"(src) : "memory");
}

// merged prep: W2 tf32 + k-permute + parity swizzle, then W1 tf32
__global__ void prep_kernel(const float* __restrict__ W2, const float* __restrict__ W1) {
    int idx = blockIdx.x * 256 + threadIdx.x;
    if (idx < E_DIM * F_DIM) {
        int n = idx >> 11;
        int c = idx & 2047;
        int t = c >> 5, q = c & 31;
        int slot = (q >> 2) ^ ((n & 1) << 2);
        int g = q & 3;
        int k = ((slot >> 2) << 4) + (slot & 3) + (g << 2);
        g_W2r[idx] = to_tf32(W2[(size_t)n * F_DIM + t * 32 + k]);
    } else {
        int i = idx - E_DIM * F_DIM;     // 0 .. F_DIM*8-1
        g_W1r[i] = to_tf32(W1[i]);
    }
}

__global__ void __launch_bounds__(NT, 2)
ffq_mma_kernel(const float* __restrict__ x, const float* __restrict__ theta,
               const float* __restrict__ b1, const float* __restrict__ b2,
               float* __restrict__ out)
{
    extern __shared__ float sm[];
    const uint32_t smB_u32 = (uint32_t)__cvta_generic_to_shared(sm);

    const int tid  = threadIdx.x;
    const int lane = tid & 31;
    const int wid  = tid >> 5;
    const int m0   = blockIdx.y * BM;
    const int n0   = blockIdx.x * BN;

    const int mw = (wid & 3) * 32;
    const int nw = (wid >> 2) * 64;
    const int fr = lane >> 2;
    const int fc = lane & 3;
    const int sw = (fr & 1) << 2;
    const int permfr = (fr >> 1) | ((fr & 1) << 2);

    // ---- q A-fragments (registers for the whole kernel) ----
    float qa[2][4];
    {
        float tc0 = cosf(__ldg(theta + fc));
        float tc1 = cosf(__ldg(theta + fc + 4));
#pragma unroll
        for (int mf = 0; mf < 2; mf++) {
            const float* x0 = x + (size_t)(m0 + mw + mf * 16 + fr) * E_DIM;
            const float* x1 = x0 + (size_t)8 * E_DIM;
            qa[mf][0] = to_tf32(cosf(__ldg(x0 + fc))     * tc0);
            qa[mf][1] = to_tf32(cosf(__ldg(x1 + fc))     * tc0);
            qa[mf][2] = to_tf32(cosf(__ldg(x0 + fc + 4)) * tc1);
            qa[mf][3] = to_tf32(cosf(__ldg(x1 + fc + 4)) * tc1);
        }
    }

    // ---- cp.async bases: row = (tid>>3) + 32j, slot = tid&7 ----
    const float* w2base = g_W2r + (size_t)(n0 + (tid >> 3)) * F_DIM + (tid & 7) * 4;
    const uint32_t dstbase = smB_u32 + (uint32_t)((tid >> 3) * 32 + (tid & 7) * 4) * 4;

    // GEMM1 W1 pointer: element [permfr][fc]; offset fb*8 per f-base
    const float* w1p = g_W1r + (size_t)permfr * 8 + fc;

    // stage-internal row step: +32 rows = 32*32 floats = 4096 BYTES
#define ISSUE_B(kt)                                                              \
    do {                                                                         \
        const uint32_t dd = dstbase + (uint32_t)((kt) % NSTG) * BSTG_BYTES;      \
        const float* ss = w2base + (kt) * BK;                                    \
        cp16(dd,            ss);                                                 \
        cp16(dd + 4096,     ss + (size_t)32 * F_DIM);                            \
        cp16(dd + 8192,     ss + (size_t)64 * F_DIM);                            \
        cp16(dd + 12288,    ss + (size_t)96 * F_DIM);                            \
        asm volatile("cp.async.commit_group;" ::: "memory");                     \
    } while (0)

    ISSUE_B(0);
    ISSUE_B(1);

    float d[2][8][4];
#pragma unroll
    for (int mf = 0; mf < 2; mf++)
#pragma unroll
        for (int nf = 0; nf < 8; nf++)
#pragma unroll
            for (int i = 0; i < 4; i++)
                d[mf][nf][i] = 0.0f;

    for (int kt = 0; kt < NKT; kt++) {
        asm volatile("cp.async.wait_group 1;" ::: "memory");
        __syncthreads();

        if (kt + 2 < NKT) {
            ISSUE_B(kt + 2);
        } else {
            asm volatile("cp.async.commit_group;" ::: "memory");   // keep count
        }

        const float* B = sm + (kt % NSTG) * (BSTG_BYTES / 4);
        const int f0 = kt * BK;

#pragma unroll
        for (int kg = 0; kg < 2; kg++) {
            // ---- GEMM1: h fragments for both k-octets, both m-tiles ----
            float af[2][2][4];   // [mf][ko][4]
#pragma unroll
            for (int ko = 0; ko < 2; ko++) {
                const int fb = f0 + kg * 16 + ko * 8;
                float bw0 = __ldg(w1p + fb * 8);
                float bw1 = __ldg(w1p + fb * 8 + 4);
                float bi0 = __ldg(b1 + fb + fc);
                float bi1 = __ldg(b1 + fb + fc + 4);
#pragma unroll
                for (int mf = 0; mf < 2; mf++) {
                    float dh[4] = {bi0, bi1, bi0, bi1};
                    mma_tf32(dh, qa[mf][0], qa[mf][1], qa[mf][2], qa[mf][3], bw0, bw1);
                    af[mf][ko][0] = to_tf32(fmaxf(dh[0], 0.0f));   // (r,   fb+fc)
                    af[mf][ko][1] = to_tf32(fmaxf(dh[2], 0.0f));   // (r+8, fb+fc)
                    af[mf][ko][2] = to_tf32(fmaxf(dh[1], 0.0f));   // (r,   fb+fc+4)
                    af[mf][ko][3] = to_tf32(fmaxf(dh[3], 0.0f));   // (r+8, fb+fc+4)
                }
            }

            // ---- GEMM2 over this kg ----
            const int slotB = (((kg << 2) | fc) ^ sw) << 2;
#pragma unroll
            for (int nf = 0; nf < 8; nf++) {
                float4 vb = *(const float4*)(B + (nw + nf * 8 + fr) * 32 + slotB);
#pragma unroll
                for (int mf = 0; mf < 2; mf++) {
                    mma_tf32(d[mf][nf],
                             af[mf][0][0], af[mf][0][1], af[mf][0][2], af[mf][0][3],
                             vb.x, vb.y);
                    mma_tf32(d[mf][nf],
                             af[mf][1][0], af[mf][1][1], af[mf][1][2], af[mf][1][3],
                             vb.z, vb.w);
                }
            }
        }
    }

    // ---- epilogue: out = d + b2 ----
    float b2v[8][2];
#pragma unroll
    for (int nf = 0; nf < 8; nf++) {
        b2v[nf][0] = __ldg(b2 + n0 + nw + nf * 8 + fc * 2);
        b2v[nf][1] = __ldg(b2 + n0 + nw + nf * 8 + fc * 2 + 1);
    }
#pragma unroll
    for (int mf = 0; mf < 2; mf++) {
#pragma unroll
        for (int i2 = 0; i2 < 2; i2++) {
            const int row = m0 + mw + mf * 16 + fr + i2 * 8;
            float* orow = out + (size_t)row * E_DIM + n0 + nw + fc * 2;
#pragma unroll
            for (int nf = 0; nf < 8; nf++) {
                float2 v;
                v.x = d[mf][nf][i2 * 2 + 0] + b2v[nf][0];
                v.y = d[mf][nf][i2 * 2 + 1] + b2v[nf][1];
                *(float2*)(orow + nf * 8) = v;
            }
        }
    }
}

extern "C" void kernel_launch(void* const* d_in, const int* in_sizes, int n_in,
                              void* d_out, int out_size) {
    const float* x     = (const float*)d_in[0];
    const float* theta = (const float*)d_in[1];
    const float* W1    = (const float*)d_in[2];
    const float* b1    = (const float*)d_in[3];
    const float* W2    = (const float*)d_in[4];
    const float* b2    = (const float*)d_in[5];
    float* out = (float*)d_out;

    const int M = in_sizes[0] / E_DIM;   // 32768

    prep_kernel<<<(E_DIM * F_DIM + F_DIM * 8) / 256, 256>>>(W2, W1);

    cudaFuncSetAttribute(ffq_mma_kernel,
                         cudaFuncAttributeMaxDynamicSharedMemorySize, SMEM_BYTES);
    dim3 grid(E_DIM / BN, M / BM);
    ffq_mma_kernel<<<grid, NT, SMEM_BYTES>>>(x, theta, b1, b2, out);
}

// round 13
// speedup vs baseline: 7.7564x; 1.7311x over previous
#include <cuda_runtime.h>
#include <cuda_fp16.h>
#include <math.h>
#include <stdint.h>

// ---------------------------------------------------------------------------
// FeedForwardQuantum, round 11: fp16 m16n8k16 (fp32 accum) — same 11-bit
// mantissa as tf32, 2x MACs per HMMA.
//   - q in 4 half2 regs (GEMM1 A-frag) for the whole kernel
//   - GEMM1 h per 16-k chunk: 2 x m16n8k8.f16 (f-blocks kb, kb+8) whose D
//     fragments ARE the m16n8k16 A operand (native col match, no permute);
//     bias = accumulator init; relu via max.f16x2 after packing
//   - B: W2 pre-converted to fp16 with the [2fc,2fc+1,2fc+8,2fc+9] slot
//     permute + chunk-pair interleave baked into gmem; 16B-granule XOR-row
//     swizzle applied at cp.async dst; consumer uses one LDS.128 per nf per
//     chunk-pair (both chunks' fragments)
//   - 3-stage cp.async pipeline, BK=64 (32 k-tiles, half the barriers)
// CTA 128x128, 256 thr, 8 warps (warp tile 32x64), 2 CTAs/SM.
// ---------------------------------------------------------------------------

#define E_DIM 512
#define F_DIM 2048
#define BM    128
#define BN    128
#define BK    64
#define NT    256
#define NKT   (F_DIM / BK)        // 32
#define NSTG  3
#define BSTG_BYTES 16384          // 128 rows x 64 halves x 2B per stage
#define SMEM_BYTES (NSTG * BSTG_BYTES)   // 49152 B

__device__ __half g_W2h[(size_t)E_DIM * F_DIM];
__device__ __half g_W1h[(size_t)F_DIM * 8];

__device__ __forceinline__ void mma_f16_k8(float* d, uint32_t a0, uint32_t a1, uint32_t b0) {
    asm volatile(
        "mma.sync.aligned.m16n8k8.row.col.f32.f16.f16.f32 "
        "{%0,%1,%2,%3}, {%4,%5}, {%6}, {%0,%1,%2,%3};\n"
        : "+f"(d[0]), "+f"(d[1]), "+f"(d[2]), "+f"(d[3])
        : "r"(a0), "r"(a1), "r"(b0));
}

__device__ __forceinline__ void mma_f16_k16(float* d, const uint32_t* a,
                                            uint32_t b0, uint32_t b1) {
    asm volatile(
        "mma.sync.aligned.m16n8k16.row.col.f32.f16.f16.f32 "
        "{%0,%1,%2,%3}, {%4,%5,%6,%7}, {%8,%9}, {%0,%1,%2,%3};\n"
        : "+f"(d[0]), "+f"(d[1]), "+f"(d[2]), "+f"(d[3])
        : "r"(a[0]), "r"(a[1]), "r"(a[2]), "r"(a[3]), "r"(b0), "r"(b1));
}

// pack (lo,hi) to f16x2 then relu via max.f16x2
__device__ __forceinline__ uint32_t relu_pack(float lo, float hi) {
    uint32_t r;
    asm("cvt.rn.f16x2.f32 %0, %2, %1;" : "=r"(r) : "f"(lo), "f"(hi));
    uint32_t z = 0;
    asm("max.f16x2 %0, %0, %1;" : "+r"(r) : "r"(z));
    return r;
}

__device__ __forceinline__ void cp16(uint32_t dst, const void* src) {
    asm volatile("cp.async.cg.shared.global [%0], [%1], 16;" :: "r"(dst), "l"(src) : "memory");
}

// prep: W2 -> fp16 with slot permute [2fc,2fc+1,2fc+8,2fc+9] and chunk-pair
// interleave baked in; W1 -> fp16 plain.
__global__ void prep_kernel(const float* __restrict__ W2, const float* __restrict__ W1) {
    int idx = blockIdx.x * 256 + threadIdx.x;
    if (idx < E_DIM * F_DIM) {
        int n  = idx >> 11;
        int jg = idx & 2047;
        int t   = jg >> 6;          // k-tile (64 halves)
        int jl  = jg & 63;
        int P   = jl >> 5;          // chunk pair
        int fc  = (jl >> 3) & 3;    // slot
        int c01 = (jl >> 2) & 1;    // chunk within pair
        int e   = jl & 3;           // element in slot
        int k = t * 64 + (P * 2 + c01) * 16 + 2 * fc + (e & 1) + ((e >> 1) << 3);
        g_W2h[idx] = __float2half(W2[((size_t)n << 11) + k]);
    } else {
        int i = idx - E_DIM * F_DIM;   // 0 .. F_DIM*8-1
        g_W1h[i] = __float2half(W1[i]);
    }
}

__global__ void __launch_bounds__(NT, 2)
ffq_mma_kernel(const float* __restrict__ x, const float* __restrict__ theta,
               const float* __restrict__ b1, const float* __restrict__ b2,
               float* __restrict__ out)
{
    extern __shared__ __half smh[];
    const uint32_t smB_u32 = (uint32_t)__cvta_generic_to_shared(smh);

    const int tid  = threadIdx.x;
    const int lane = tid & 31;
    const int wid  = tid >> 5;
    const int m0   = blockIdx.y * BM;
    const int n0   = blockIdx.x * BN;

    const int mw = (wid & 3) * 32;
    const int nw = (wid >> 2) * 64;
    const int fr = lane >> 2;
    const int fc = lane & 3;

    // ---- q A-fragments (half2 pairs, whole kernel) ----
    uint32_t qa[2][2];
    {
        float tc0 = cosf(__ldg(theta + 2 * fc));
        float tc1 = cosf(__ldg(theta + 2 * fc + 1));
#pragma unroll
        for (int mf = 0; mf < 2; mf++) {
            const float* x0 = x + (size_t)(m0 + mw + mf * 16 + fr) * E_DIM;
            const float* x1 = x0 + (size_t)8 * E_DIM;
            float q00 = cosf(__ldg(x0 + 2 * fc))     * tc0;
            float q01 = cosf(__ldg(x0 + 2 * fc + 1)) * tc1;
            float q10 = cosf(__ldg(x1 + 2 * fc))     * tc0;
            float q11 = cosf(__ldg(x1 + 2 * fc + 1)) * tc1;
            asm("cvt.rn.f16x2.f32 %0, %2, %1;" : "=r"(qa[mf][0]) : "f"(q00), "f"(q01));
            asm("cvt.rn.f16x2.f32 %0, %2, %1;" : "=r"(qa[mf][1]) : "f"(q10), "f"(q11));
        }
    }

    // ---- cp.async bases: row = (tid>>3) + 32j, 16B granule = tid&7 ----
    const char* w2src = (const char*)g_W2h
                      + (size_t)(n0 + (tid >> 3)) * F_DIM * 2 + (tid & 7) * 16;
    const int dg = (tid & 7) ^ ((tid >> 3) & 7);
    const uint32_t dstbase = smB_u32 + (uint32_t)((tid >> 3) * 128 + dg * 16);

#define ISSUE_B(kt)                                                              \
    do {                                                                         \
        const uint32_t dd = dstbase + (uint32_t)((kt) % NSTG) * BSTG_BYTES;      \
        const char* ss = w2src + (size_t)(kt) * 128;                             \
        cp16(dd,          ss);                                                   \
        cp16(dd + 4096,   ss + (size_t)32 * F_DIM * 2);                          \
        cp16(dd + 8192,   ss + (size_t)64 * F_DIM * 2);                          \
        cp16(dd + 12288,  ss + (size_t)96 * F_DIM * 2);                          \
        asm volatile("cp.async.commit_group;" ::: "memory");                     \
    } while (0)

    ISSUE_B(0);
    ISSUE_B(1);

    float d[2][8][4];
#pragma unroll
    for (int mf = 0; mf < 2; mf++)
#pragma unroll
        for (int nf = 0; nf < 8; nf++)
#pragma unroll
            for (int i = 0; i < 4; i++)
                d[mf][nf][i] = 0.0f;

    for (int kt = 0; kt < NKT; kt++) {
        asm volatile("cp.async.wait_group 1;" ::: "memory");
        __syncthreads();

        if (kt + 2 < NKT) {
            ISSUE_B(kt + 2);
        } else {
            asm volatile("cp.async.commit_group;" ::: "memory");   // keep count
        }

        const __half* B = smh + (kt % NSTG) * (BSTG_BYTES / 2);
        const int f0 = kt * BK;

#pragma unroll
        for (int P = 0; P < 2; P++) {
            // ---- GEMM1: A-fragments for chunks 2P, 2P+1 ----
            uint32_t af[2][2][4];   // [c01][mf][R0..R3]
#pragma unroll
            for (int c01 = 0; c01 < 2; c01++) {
                const int kb = f0 + (P * 2 + c01) * 16;
#pragma unroll
                for (int fb2 = 0; fb2 < 2; fb2++) {
                    const int fb = kb + fb2 * 8;
                    uint32_t w1f = __ldg((const uint32_t*)(g_W1h + (size_t)(fb + fr) * 8 + 2 * fc));
                    float2 bi = *(const float2*)(b1 + fb + 2 * fc);
#pragma unroll
                    for (int mf = 0; mf < 2; mf++) {
                        float dh[4] = {bi.x, bi.y, bi.x, bi.y};
                        mma_f16_k8(dh, qa[mf][0], qa[mf][1], w1f);
                        af[c01][mf][fb2 * 2 + 0] = relu_pack(dh[0], dh[1]);   // row fr
                        af[c01][mf][fb2 * 2 + 1] = relu_pack(dh[2], dh[3]);   // row fr+8
                    }
                }
            }

            // ---- GEMM2 over chunk pair P ----
            const int gr = (((P * 4) + fc) ^ fr) * 8;    // halves (16B granule)
#pragma unroll
            for (int nf = 0; nf < 8; nf++) {
                uint4 vb = *(const uint4*)(B + (nw + nf * 8 + fr) * 64 + gr);
#pragma unroll
                for (int mf = 0; mf < 2; mf++) {
                    mma_f16_k16(d[mf][nf], af[0][mf], vb.x, vb.y);
                    mma_f16_k16(d[mf][nf], af[1][mf], vb.z, vb.w);
                }
            }
        }
    }

    // ---- epilogue: out = d + b2 ----
    float b2v[8][2];
#pragma unroll
    for (int nf = 0; nf < 8; nf++) {
        b2v[nf][0] = __ldg(b2 + n0 + nw + nf * 8 + fc * 2);
        b2v[nf][1] = __ldg(b2 + n0 + nw + nf * 8 + fc * 2 + 1);
    }
#pragma unroll
    for (int mf = 0; mf < 2; mf++) {
#pragma unroll
        for (int i2 = 0; i2 < 2; i2++) {
            const int row = m0 + mw + mf * 16 + fr + i2 * 8;
            float* orow = out + (size_t)row * E_DIM + n0 + nw + fc * 2;
#pragma unroll
            for (int nf = 0; nf < 8; nf++) {
                float2 v;
                v.x = d[mf][nf][i2 * 2 + 0] + b2v[nf][0];
                v.y = d[mf][nf][i2 * 2 + 1] + b2v[nf][1];
                *(float2*)(orow + nf * 8) = v;
            }
        }
    }
}

extern "C" void kernel_launch(void* const* d_in, const int* in_sizes, int n_in,
                              void* d_out, int out_size) {
    const float* x     = (const float*)d_in[0];
    const float* theta = (const float*)d_in[1];
    const float* W1    = (const float*)d_in[2];
    const float* b1    = (const float*)d_in[3];
    const float* W2    = (const float*)d_in[4];
    const float* b2    = (const float*)d_in[5];
    float* out = (float*)d_out;

    const int M = in_sizes[0] / E_DIM;   // 32768

    prep_kernel<<<(E_DIM * F_DIM + F_DIM * 8) / 256, 256>>>(W2, W1);

    cudaFuncSetAttribute(ffq_mma_kernel,
                         cudaFuncAttributeMaxDynamicSharedMemorySize, SMEM_BYTES);
    dim3 grid(E_DIM / BN, M / BM);
    ffq_mma_kernel<<<grid, NT, SMEM_BYTES>>>(x, theta, b1, b2, out);
}